// round 11
// baseline (speedup 1.0000x reference)
#include <cuda_runtime.h>
#include <math.h>

// Combined per-interval cubic: f(x) ≈ ((P.x*u+P.y)*u+P.z)*u+P.w,
// u = 13x - i, i = clamp(floor(13x), 3, 9). P folds ws*spline (exact) and
// wb*silu (per-interval cubic Chebyshev fit, err ~6e-6).
__device__ float4 g_poly[7];   // only for the defensive scalar-tail kernel

// ---------------------------------------------------------------------------
// In-kernel table build, pure fp32 (threads 0..6; ~60 instrs).
// ---------------------------------------------------------------------------
__device__ __forceinline__ void build_poly_smem(float4* sPoly,
                                                const float* __restrict__ coef,
                                                const float* __restrict__ wbp,
                                                const float* __restrict__ wsp,
                                                bool writeGlobal) {
    int iv = threadIdx.x;            // 0..6 -> knot interval i = iv+3
    if (iv < 7) {
        float wb = __ldg(wbp);
        float ws = __ldg(wsp);
        int i = iv + 3;

        // exact uniform cubic B-spline segment, monomial in u
        float c0 = __ldg(coef + iv + 0);
        float c1 = __ldg(coef + iv + 1);
        float c2 = __ldg(coef + iv + 2);
        float c3 = __ldg(coef + iv + 3);
        const float s = 1.0f / 6.0f;
        float sa = (-c0 + 3.0f * c1 - 3.0f * c2 + c3) * s;
        float sb = ( 3.0f * c0 - 6.0f * c1 + 3.0f * c2) * s;
        float sc = (-3.0f * c0 + 3.0f * c2) * s;
        float sd = ( c0 + 4.0f * c1 + c2) * s;

        // cubic Chebyshev fit of silu over this interval's served u-range
        float ulo = (iv == 0) ? -3.0f : 0.0f;
        float uhi = (iv == 6) ?  4.0f : 1.0f;
        float mid = 0.5f * (ulo + uhi), rad = 0.5f * (uhi - ulo);
        const float cn0 =  0.92387953f, cn1 = 0.38268343f;
        float un[4], fv[4];
        un[0] = mid + rad * cn0;
        un[1] = mid + rad * cn1;
        un[2] = mid - rad * cn1;
        un[3] = mid - rad * cn0;
        #pragma unroll
        for (int k = 0; k < 4; k++) {
            float xx = (un[k] + (float)i) * (1.0f / 13.0f);
            fv[k] = xx / (1.0f + __expf(-xx));          // silu(xx)
        }
        float d0    = fv[0];
        float d01   = (fv[1] - fv[0]) / (un[1] - un[0]);
        float d12   = (fv[2] - fv[1]) / (un[2] - un[1]);
        float d23   = (fv[3] - fv[2]) / (un[3] - un[2]);
        float d012  = (d12 - d01) / (un[2] - un[0]);
        float d123  = (d23 - d12) / (un[3] - un[1]);
        float d0123 = (d123 - d012) / (un[3] - un[0]);
        float e0 = un[0] + un[1], e01 = un[0] * un[1];
        float A3 = d0123;
        float A2 = d012 - d0123 * (un[0] + un[1] + un[2]);
        float A1 = d01 - d012 * e0 + d0123 * (e01 + un[0] * un[2] + un[1] * un[2]);
        float A0 = d0 - d01 * un[0] + d012 * e01 - d0123 * e01 * un[2];

        float4 p;
        p.x = fmaf(ws, sa, wb * A3);
        p.y = fmaf(ws, sb, wb * A2);
        p.z = fmaf(ws, sc, wb * A1);
        p.w = fmaf(ws, sd, wb * A0);
        sPoly[iv] = p;
        if (writeGlobal) g_poly[iv] = p;
    }
}

__device__ __forceinline__ float eval_one(float x, const float4* __restrict__ sPoly) {
    float fi = x * 13.0f;
    int j = (int)fi;                 // x >= 0: truncation == floor
    j = min(max(j, 3), 9);           // scipy clip -> polynomial extrapolation
    float u = fi - (float)j;
    float4 p = sPoly[j - 3];         // 7x16B: distinct banks + broadcast dedup
    return fmaf(fmaf(fmaf(p.x, u, p.y), u, p.z), u, p.w);
}

// 256-bit load with L2 evict_last: x is re-read every graph replay; pin it.
struct F8 { float4 a, b; };
__device__ __forceinline__ F8 ldg_evict_last8(const void* p) {
    unsigned r0, r1, r2, r3, r4, r5, r6, r7;
    asm volatile("ld.global.nc.L2::evict_last.v8.b32 {%0,%1,%2,%3,%4,%5,%6,%7}, [%8];"
                 : "=r"(r0), "=r"(r1), "=r"(r2), "=r"(r3),
                   "=r"(r4), "=r"(r5), "=r"(r6), "=r"(r7)
                 : "l"(p));
    F8 v;
    v.a.x = __uint_as_float(r0); v.a.y = __uint_as_float(r1);
    v.a.z = __uint_as_float(r2); v.a.w = __uint_as_float(r3);
    v.b.x = __uint_as_float(r4); v.b.y = __uint_as_float(r5);
    v.b.z = __uint_as_float(r6); v.b.w = __uint_as_float(r7);
    return v;
}

#define V8_PER_THREAD 2   // float8s per thread per loop iteration (64 B)

__global__ void __launch_bounds__(256)
residual_act_fused_kernel(const float* __restrict__ x,
                          float4* __restrict__ out4,
                          int n8, int hasTail,
                          const float* __restrict__ coef,
                          const float* __restrict__ wbp,
                          const float* __restrict__ wsp) {
    __shared__ float4 sPoly[7];
    build_poly_smem(sPoly, coef, wbp, wsp, hasTail && blockIdx.x == 0);
    __syncthreads();

    const int tile = 256 * V8_PER_THREAD;         // float8s per block-iter
    for (int base0 = blockIdx.x * tile; base0 < n8; base0 += gridDim.x * tile) {
        int base = base0 + threadIdx.x;           // float8 index
        if (base0 + tile <= n8) {
            F8 xv[V8_PER_THREAD];
            #pragma unroll
            for (int k = 0; k < V8_PER_THREAD; k++)
                xv[k] = ldg_evict_last8(x + (size_t)(base + k * 256) * 8);
            #pragma unroll
            for (int k = 0; k < V8_PER_THREAD; k++) {
                float4 oa, ob;
                oa.x = eval_one(xv[k].a.x, sPoly);
                oa.y = eval_one(xv[k].a.y, sPoly);
                oa.z = eval_one(xv[k].a.z, sPoly);
                oa.w = eval_one(xv[k].a.w, sPoly);
                ob.x = eval_one(xv[k].b.x, sPoly);
                ob.y = eval_one(xv[k].b.y, sPoly);
                ob.z = eval_one(xv[k].b.z, sPoly);
                ob.w = eval_one(xv[k].b.w, sPoly);
                // streaming stores: evict-first so output doesn't evict x from L2
                __stcs(out4 + (size_t)(base + k * 256) * 2,     oa);
                __stcs(out4 + (size_t)(base + k * 256) * 2 + 1, ob);
            }
        } else {
            #pragma unroll
            for (int k = 0; k < V8_PER_THREAD; k++) {
                int idx = base + k * 256;
                if (idx < n8) {
                    F8 xv = ldg_evict_last8(x + (size_t)idx * 8);
                    float4 oa, ob;
                    oa.x = eval_one(xv.a.x, sPoly);
                    oa.y = eval_one(xv.a.y, sPoly);
                    oa.z = eval_one(xv.a.z, sPoly);
                    oa.w = eval_one(xv.a.w, sPoly);
                    ob.x = eval_one(xv.b.x, sPoly);
                    ob.y = eval_one(xv.b.y, sPoly);
                    ob.z = eval_one(xv.b.z, sPoly);
                    ob.w = eval_one(xv.b.w, sPoly);
                    __stcs(out4 + (size_t)idx * 2,     oa);
                    __stcs(out4 + (size_t)idx * 2 + 1, ob);
                }
            }
        }
    }
}

// Scalar tail (n % 8 != 0 — defensive; n = 2^24 in practice so never launched).
__global__ void residual_act_tail_kernel(const float* __restrict__ x,
                                         float* __restrict__ out,
                                         int start, int n) {
    int idx = start + blockIdx.x * blockDim.x + threadIdx.x;
    if (idx < n) {
        float fi = x[idx] * 13.0f;
        int j = min(max((int)fi, 3), 9);
        float u = fi - (float)j;
        float4 p = g_poly[j - 3];
        out[idx] = fmaf(fmaf(fmaf(p.x, u, p.y), u, p.z), u, p.w);
    }
}

extern "C" void kernel_launch(void* const* d_in, const int* in_sizes, int n_in,
                              void* d_out, int out_size) {
    const float* x    = (const float*)d_in[0];   // [N] activations
    const float* coef = (const float*)d_in[1];   // [10] spline coefficients
    const float* wb   = (const float*)d_in[2];   // [1] w_basis
    const float* ws   = (const float*)d_in[3];   // [1] w_spline
    float* out        = (float*)d_out;

    int n    = in_sizes[0];
    int n8   = n / 8;
    int tail = n - n8 * 8;

    if (n8 > 0) {
        const int tile = 256 * V8_PER_THREAD;
        int work_blocks = (n8 + tile - 1) / tile;
        // Balanced persistent grid: every block runs exactly `iters` tiles.
        int cap   = 1184;
        int iters = (work_blocks + cap - 1) / cap;
        int blocks = (work_blocks + iters - 1) / iters;
        residual_act_fused_kernel<<<blocks, 256>>>(
            x, (float4*)out, n8, tail > 0 ? 1 : 0, coef, wb, ws);
    }
    if (tail > 0) {
        residual_act_tail_kernel<<<1, 256>>>(x, out, n8 * 8, n);
    }
}

// round 13
// speedup vs baseline: 1.1795x; 1.1795x over previous
#include <cuda_runtime.h>
#include <math.h>

// Combined per-interval cubic: f(x) ≈ ((P.x*u+P.y)*u+P.z)*u+P.w,
// u = 13x - i, i = clamp(floor(13x), 3, 9). P folds ws*spline (exact) and
// wb*silu (per-interval cubic Chebyshev fit, err ~6e-6).
__device__ float4 g_poly[7];   // only for the defensive scalar-tail kernel

// ---------------------------------------------------------------------------
// In-kernel table build, pure fp32 (threads 0..6; ~60 instrs).
// ---------------------------------------------------------------------------
__device__ __forceinline__ void build_poly_smem(float4* sPoly,
                                                const float* __restrict__ coef,
                                                const float* __restrict__ wbp,
                                                const float* __restrict__ wsp,
                                                bool writeGlobal) {
    int iv = threadIdx.x;            // 0..6 -> knot interval i = iv+3
    if (iv < 7) {
        float wb = __ldg(wbp);
        float ws = __ldg(wsp);
        int i = iv + 3;

        // exact uniform cubic B-spline segment, monomial in u
        float c0 = __ldg(coef + iv + 0);
        float c1 = __ldg(coef + iv + 1);
        float c2 = __ldg(coef + iv + 2);
        float c3 = __ldg(coef + iv + 3);
        const float s = 1.0f / 6.0f;
        float sa = (-c0 + 3.0f * c1 - 3.0f * c2 + c3) * s;
        float sb = ( 3.0f * c0 - 6.0f * c1 + 3.0f * c2) * s;
        float sc = (-3.0f * c0 + 3.0f * c2) * s;
        float sd = ( c0 + 4.0f * c1 + c2) * s;

        // cubic Chebyshev fit of silu over this interval's served u-range
        float ulo = (iv == 0) ? -3.0f : 0.0f;
        float uhi = (iv == 6) ?  4.0f : 1.0f;
        float mid = 0.5f * (ulo + uhi), rad = 0.5f * (uhi - ulo);
        const float cn0 =  0.92387953f, cn1 = 0.38268343f;
        float un[4], fv[4];
        un[0] = mid + rad * cn0;
        un[1] = mid + rad * cn1;
        un[2] = mid - rad * cn1;
        un[3] = mid - rad * cn0;
        #pragma unroll
        for (int k = 0; k < 4; k++) {
            float xx = (un[k] + (float)i) * (1.0f / 13.0f);
            fv[k] = xx / (1.0f + __expf(-xx));          // silu(xx)
        }
        float d0    = fv[0];
        float d01   = (fv[1] - fv[0]) / (un[1] - un[0]);
        float d12   = (fv[2] - fv[1]) / (un[2] - un[1]);
        float d23   = (fv[3] - fv[2]) / (un[3] - un[2]);
        float d012  = (d12 - d01) / (un[2] - un[0]);
        float d123  = (d23 - d12) / (un[3] - un[1]);
        float d0123 = (d123 - d012) / (un[3] - un[0]);
        float e0 = un[0] + un[1], e01 = un[0] * un[1];
        float A3 = d0123;
        float A2 = d012 - d0123 * (un[0] + un[1] + un[2]);
        float A1 = d01 - d012 * e0 + d0123 * (e01 + un[0] * un[2] + un[1] * un[2]);
        float A0 = d0 - d01 * un[0] + d012 * e01 - d0123 * e01 * un[2];

        float4 p;
        p.x = fmaf(ws, sa, wb * A3);
        p.y = fmaf(ws, sb, wb * A2);
        p.z = fmaf(ws, sc, wb * A1);
        p.w = fmaf(ws, sd, wb * A0);
        sPoly[iv] = p;
        if (writeGlobal) g_poly[iv] = p;
    }
}

__device__ __forceinline__ float eval_one(float x, const float4* __restrict__ sPoly) {
    float fi = x * 13.0f;
    int j = (int)fi;                 // x >= 0: truncation == floor
    j = min(max(j, 3), 9);           // scipy clip -> polynomial extrapolation
    float u = fi - (float)j;
    float4 p = sPoly[j - 3];         // 7x16B: distinct banks + broadcast dedup
    return fmaf(fmaf(fmaf(p.x, u, p.y), u, p.z), u, p.w);
}

// 256-bit streaming store (evict-first): one STG.256 instead of two STG.128.
__device__ __forceinline__ void stcs8(void* p, float4 a, float4 b) {
    unsigned long long d0 = ((unsigned long long)__float_as_uint(a.y) << 32) | __float_as_uint(a.x);
    unsigned long long d1 = ((unsigned long long)__float_as_uint(a.w) << 32) | __float_as_uint(a.z);
    unsigned long long d2 = ((unsigned long long)__float_as_uint(b.y) << 32) | __float_as_uint(b.x);
    unsigned long long d3 = ((unsigned long long)__float_as_uint(b.w) << 32) | __float_as_uint(b.z);
    asm volatile("st.global.cs.v4.b64 [%0], {%1,%2,%3,%4};"
                 :: "l"(p), "l"(d0), "l"(d1), "l"(d2), "l"(d3) : "memory");
}

#define V8_PER_THREAD 2   // float8s per thread per loop iteration (64 B)

__global__ void __launch_bounds__(256)
residual_act_fused_kernel(const float4* __restrict__ x4,
                          float* __restrict__ out,
                          int n8, int hasTail,
                          const float* __restrict__ coef,
                          const float* __restrict__ wbp,
                          const float* __restrict__ wsp) {
    __shared__ float4 sPoly[7];
    build_poly_smem(sPoly, coef, wbp, wsp, hasTail && blockIdx.x == 0);
    __syncthreads();

    const int tile = 256 * V8_PER_THREAD;         // float8s per block-iter
    for (int base0 = blockIdx.x * tile; base0 < n8; base0 += gridDim.x * tile) {
        int base = base0 + threadIdx.x;           // float8 index
        if (base0 + tile <= n8) {
            float4 xa[V8_PER_THREAD], xb[V8_PER_THREAD];
            #pragma unroll
            for (int k = 0; k < V8_PER_THREAD; k++) {
                int f4i = (base + k * 256) * 2;   // float4 index
                xa[k] = __ldg(x4 + f4i);
                xb[k] = __ldg(x4 + f4i + 1);
            }
            #pragma unroll
            for (int k = 0; k < V8_PER_THREAD; k++) {
                float4 oa, ob;
                oa.x = eval_one(xa[k].x, sPoly);
                oa.y = eval_one(xa[k].y, sPoly);
                oa.z = eval_one(xa[k].z, sPoly);
                oa.w = eval_one(xa[k].w, sPoly);
                ob.x = eval_one(xb[k].x, sPoly);
                ob.y = eval_one(xb[k].y, sPoly);
                ob.z = eval_one(xb[k].z, sPoly);
                ob.w = eval_one(xb[k].w, sPoly);
                stcs8(out + (size_t)(base + k * 256) * 8, oa, ob);
            }
        } else {
            #pragma unroll
            for (int k = 0; k < V8_PER_THREAD; k++) {
                int idx = base + k * 256;
                if (idx < n8) {
                    float4 xa = __ldg(x4 + idx * 2);
                    float4 xb = __ldg(x4 + idx * 2 + 1);
                    float4 oa, ob;
                    oa.x = eval_one(xa.x, sPoly);
                    oa.y = eval_one(xa.y, sPoly);
                    oa.z = eval_one(xa.z, sPoly);
                    oa.w = eval_one(xa.w, sPoly);
                    ob.x = eval_one(xb.x, sPoly);
                    ob.y = eval_one(xb.y, sPoly);
                    ob.z = eval_one(xb.z, sPoly);
                    ob.w = eval_one(xb.w, sPoly);
                    stcs8(out + (size_t)idx * 8, oa, ob);
                }
            }
        }
    }
}

// Scalar tail (n % 8 != 0 — defensive; n = 2^24 in practice so never launched).
__global__ void residual_act_tail_kernel(const float* __restrict__ x,
                                         float* __restrict__ out,
                                         int start, int n) {
    int idx = start + blockIdx.x * blockDim.x + threadIdx.x;
    if (idx < n) {
        float fi = x[idx] * 13.0f;
        int j = min(max((int)fi, 3), 9);
        float u = fi - (float)j;
        float4 p = g_poly[j - 3];
        out[idx] = fmaf(fmaf(fmaf(p.x, u, p.y), u, p.z), u, p.w);
    }
}

extern "C" void kernel_launch(void* const* d_in, const int* in_sizes, int n_in,
                              void* d_out, int out_size) {
    const float* x    = (const float*)d_in[0];   // [N] activations
    const float* coef = (const float*)d_in[1];   // [10] spline coefficients
    const float* wb   = (const float*)d_in[2];   // [1] w_basis
    const float* ws   = (const float*)d_in[3];   // [1] w_spline
    float* out        = (float*)d_out;

    int n    = in_sizes[0];
    int n8   = n / 8;
    int tail = n - n8 * 8;

    if (n8 > 0) {
        const int tile = 256 * V8_PER_THREAD;
        int work_blocks = (n8 + tile - 1) / tile;
        // Balanced persistent grid: every block runs exactly `iters` tiles.
        int cap   = 1184;
        int iters = (work_blocks + cap - 1) / cap;
        int blocks = (work_blocks + iters - 1) / iters;
        residual_act_fused_kernel<<<blocks, 256>>>(
            (const float4*)x, out, n8, tail > 0 ? 1 : 0, coef, wb, ws);
    }
    if (tail > 0) {
        residual_act_tail_kernel<<<1, 256>>>(x, out, n8 * 8, n);
    }
}

// round 14
// speedup vs baseline: 1.2847x; 1.0892x over previous
#include <cuda_runtime.h>
#include <math.h>

// Combined per-interval cubic: f(x) ≈ ((P.x*u+P.y)*u+P.z)*u+P.w,
// u = 13x - i, i = clamp(floor(13x), 3, 9). P folds ws*spline (exact) and
// wb*silu (per-interval cubic Chebyshev fit, err ~6e-6).
__device__ float4 g_poly[7];   // only for the defensive scalar-tail kernel

// ---------------------------------------------------------------------------
// In-kernel table build, pure fp32 (threads 0..6; ~60 instrs).
// ---------------------------------------------------------------------------
__device__ __forceinline__ void build_poly_smem(float4* sPoly,
                                                const float* __restrict__ coef,
                                                const float* __restrict__ wbp,
                                                const float* __restrict__ wsp,
                                                bool writeGlobal) {
    int iv = threadIdx.x;            // 0..6 -> knot interval i = iv+3
    if (iv < 7) {
        float wb = __ldg(wbp);
        float ws = __ldg(wsp);
        int i = iv + 3;

        // exact uniform cubic B-spline segment, monomial in u
        float c0 = __ldg(coef + iv + 0);
        float c1 = __ldg(coef + iv + 1);
        float c2 = __ldg(coef + iv + 2);
        float c3 = __ldg(coef + iv + 3);
        const float s = 1.0f / 6.0f;
        float sa = (-c0 + 3.0f * c1 - 3.0f * c2 + c3) * s;
        float sb = ( 3.0f * c0 - 6.0f * c1 + 3.0f * c2) * s;
        float sc = (-3.0f * c0 + 3.0f * c2) * s;
        float sd = ( c0 + 4.0f * c1 + c2) * s;

        // cubic Chebyshev fit of silu over this interval's served u-range
        float ulo = (iv == 0) ? -3.0f : 0.0f;
        float uhi = (iv == 6) ?  4.0f : 1.0f;
        float mid = 0.5f * (ulo + uhi), rad = 0.5f * (uhi - ulo);
        const float cn0 =  0.92387953f, cn1 = 0.38268343f;
        float un[4], fv[4];
        un[0] = mid + rad * cn0;
        un[1] = mid + rad * cn1;
        un[2] = mid - rad * cn1;
        un[3] = mid - rad * cn0;
        #pragma unroll
        for (int k = 0; k < 4; k++) {
            float xx = (un[k] + (float)i) * (1.0f / 13.0f);
            fv[k] = xx / (1.0f + __expf(-xx));          // silu(xx)
        }
        float d0    = fv[0];
        float d01   = (fv[1] - fv[0]) / (un[1] - un[0]);
        float d12   = (fv[2] - fv[1]) / (un[2] - un[1]);
        float d23   = (fv[3] - fv[2]) / (un[3] - un[2]);
        float d012  = (d12 - d01) / (un[2] - un[0]);
        float d123  = (d23 - d12) / (un[3] - un[1]);
        float d0123 = (d123 - d012) / (un[3] - un[0]);
        float e0 = un[0] + un[1], e01 = un[0] * un[1];
        float A3 = d0123;
        float A2 = d012 - d0123 * (un[0] + un[1] + un[2]);
        float A1 = d01 - d012 * e0 + d0123 * (e01 + un[0] * un[2] + un[1] * un[2]);
        float A0 = d0 - d01 * un[0] + d012 * e01 - d0123 * e01 * un[2];

        float4 p;
        p.x = fmaf(ws, sa, wb * A3);
        p.y = fmaf(ws, sb, wb * A2);
        p.z = fmaf(ws, sc, wb * A1);
        p.w = fmaf(ws, sd, wb * A0);
        sPoly[iv] = p;
        if (writeGlobal) g_poly[iv] = p;
    }
}

__device__ __forceinline__ float eval_one(float x, const float4* __restrict__ sPoly) {
    float fi = x * 13.0f;
    int j = (int)fi;                 // x >= 0: truncation == floor
    j = min(max(j, 3), 9);           // scipy clip -> polynomial extrapolation
    float u = fi - (float)j;
    float4 p = sPoly[j - 3];         // 7x16B: distinct banks + broadcast dedup
    return fmaf(fmaf(fmaf(p.x, u, p.y), u, p.z), u, p.w);
}

#define V_PER_THREAD 4   // float4s per thread per loop iteration (64 B)

__global__ void __launch_bounds__(256, 8)
residual_act_fused_kernel(const float4* __restrict__ x4,
                          float4* __restrict__ out4,
                          int n4, int hasTail,
                          const float* __restrict__ coef,
                          const float* __restrict__ wbp,
                          const float* __restrict__ wsp) {
    __shared__ float4 sPoly[7];
    build_poly_smem(sPoly, coef, wbp, wsp, hasTail && blockIdx.x == 0);
    __syncthreads();

    const int tile = 256 * V_PER_THREAD;          // float4s per block-iter
    for (int base0 = blockIdx.x * tile; base0 < n4; base0 += gridDim.x * tile) {
        int base = base0 + threadIdx.x;
        if (base0 + tile <= n4) {
            float4 xv[V_PER_THREAD];
            #pragma unroll
            for (int k = 0; k < V_PER_THREAD; k++)
                xv[k] = x4[base + k * 256];
            #pragma unroll
            for (int k = 0; k < V_PER_THREAD; k++) {
                float4 ov;
                ov.x = eval_one(xv[k].x, sPoly);
                ov.y = eval_one(xv[k].y, sPoly);
                ov.z = eval_one(xv[k].z, sPoly);
                ov.w = eval_one(xv[k].w, sPoly);
                // streaming store: evict-first so output doesn't evict x from L2
                __stcs(out4 + base + k * 256, ov);
            }
        } else {
            #pragma unroll
            for (int k = 0; k < V_PER_THREAD; k++) {
                int idx = base + k * 256;
                if (idx < n4) {
                    float4 xv = x4[idx];
                    float4 ov;
                    ov.x = eval_one(xv.x, sPoly);
                    ov.y = eval_one(xv.y, sPoly);
                    ov.z = eval_one(xv.z, sPoly);
                    ov.w = eval_one(xv.w, sPoly);
                    __stcs(out4 + idx, ov);
                }
            }
        }
    }
}

// Scalar tail (n % 4 != 0 — defensive; n = 2^24 in practice so never launched).
__global__ void residual_act_tail_kernel(const float* __restrict__ x,
                                         float* __restrict__ out,
                                         int start, int n) {
    int idx = start + blockIdx.x * blockDim.x + threadIdx.x;
    if (idx < n) {
        float fi = x[idx] * 13.0f;
        int j = min(max((int)fi, 3), 9);
        float u = fi - (float)j;
        float4 p = g_poly[j - 3];
        out[idx] = fmaf(fmaf(fmaf(p.x, u, p.y), u, p.z), u, p.w);
    }
}

extern "C" void kernel_launch(void* const* d_in, const int* in_sizes, int n_in,
                              void* d_out, int out_size) {
    const float* x    = (const float*)d_in[0];   // [N] activations
    const float* coef = (const float*)d_in[1];   // [10] spline coefficients
    const float* wb   = (const float*)d_in[2];   // [1] w_basis
    const float* ws   = (const float*)d_in[3];   // [1] w_spline
    float* out        = (float*)d_out;

    int n    = in_sizes[0];
    int n4   = n / 4;
    int tail = n - n4 * 4;

    if (n4 > 0) {
        const int tile = 256 * V_PER_THREAD;
        int work_blocks = (n4 + tile - 1) / tile;
        // Balanced persistent grid: every block runs exactly `iters` tiles.
        // (4096 tiles -> iters=4 -> 1024 blocks; single resident wave, no straggler)
        int cap   = 1184;
        int iters = (work_blocks + cap - 1) / cap;
        int blocks = (work_blocks + iters - 1) / iters;
        residual_act_fused_kernel<<<blocks, 256>>>(
            (const float4*)x, (float4*)out, n4, tail > 0 ? 1 : 0, coef, wb, ws);
    }
    if (tail > 0) {
        residual_act_tail_kernel<<<1, 256>>>(x, out, n4 * 4, n);
    }
}